// round 15
// baseline (speedup 1.0000x reference)
#include <cuda_runtime.h>

// CategoryAwareGate: B=8, C=16, H=W=256, HID=32, N = B*H*W = 524288.
// d_out packing (float32): fused_logits[8,16,256,256] (8388608),
// expert_preferences[16,2] (32), dynamic_weights[N,16,2] (16777216).
//
// R15 = R14 + softmax normalization folded into the exponent:
//   exp(x)/ss = ex2(x*log2e - lg2(ss))  -> FFMA+MUFU instead of FMUL+MUFU+FMUL.
// Removes 64 FMULs/thread from the fma pipe (the most-loaded pipe).
// Chassis: block=128, 2 slots/thread, 7 CTAs/SM, logit-prefetch pipeline,
// smem weights, stride-18 dw staging, coalesced drain, in-kernel pref copy.

static constexpr long FUSED_ELEMS = 8L * 16 * 65536;  // 8388608
static constexpr int STR = 18;                         // floats per w-row
static constexpr int SMEM_BYTES = 8192 + 64 + 256 * STR * 4;  // 26688
static constexpr float L2E = 1.4426950408889634f;      // log2(e)

__device__ __forceinline__ unsigned long long pk2(float a, float b) {
    unsigned long long r;
    asm("mov.b64 %0, {%1, %2};" : "=l"(r) : "f"(a), "f"(b));
    return r;
}
__device__ __forceinline__ void upk2(unsigned long long v, float& a, float& b) {
    asm("mov.b64 {%0, %1}, %2;" : "=f"(a), "=f"(b) : "l"(v));
}
__device__ __forceinline__ unsigned long long fma2(unsigned long long a,
                                                   unsigned long long b,
                                                   unsigned long long c) {
    unsigned long long r;
    asm("fma.rn.f32x2 %0, %1, %2, %3;" : "=l"(r) : "l"(a), "l"(b), "l"(c));
    return r;
}
// packed relu: two scalar max.f32 on the halves (no f32x2 min/max in PTX)
__device__ __forceinline__ unsigned long long relu2(unsigned long long v) {
    unsigned long long r;
    asm("{\n\t"
        ".reg .f32 lo, hi;\n\t"
        "mov.b64 {lo, hi}, %1;\n\t"
        "max.f32 lo, lo, 0f00000000;\n\t"
        "max.f32 hi, hi, 0f00000000;\n\t"
        "mov.b64 %0, {lo, hi};\n\t"
        "}" : "=l"(r) : "l"(v));
    return r;
}
__device__ __forceinline__ float ex2f(float x) {
    float r;
    asm("ex2.approx.f32 %0, %1;" : "=f"(r) : "f"(x));
    return r;
}
__device__ __forceinline__ float lg2f(float x) {
    float r;
    asm("lg2.approx.f32 %0, %1;" : "=f"(r) : "f"(x));
    return r;
}

__global__ void __launch_bounds__(128, 7)
gate_fuse_kernel(const float* __restrict__ swin, const float* __restrict__ gru,
                 const float* __restrict__ W1, const float* __restrict__ b1,
                 const float* __restrict__ W2, const float* __restrict__ b2,
                 const float* __restrict__ pref,
                 float* __restrict__ fused, float* __restrict__ dw,
                 float* __restrict__ prefout) {
    extern __shared__ __align__(16) unsigned char smem_raw[];
    unsigned long long* sw = reinterpret_cast<unsigned long long*>(smem_raw);  // 1024 u64
    float* sb2d = reinterpret_cast<float*>(smem_raw + 8192);                   // 16 floats
    float* wbuf = reinterpret_cast<float*>(smem_raw + 8192 + 64);              // 256 x 18

    const int tid = threadIdx.x;
    const int warp = tid >> 5;
    const int lane = tid & 31;

    // expert_preferences pass-through (replaces the memcpy graph node).
    if (blockIdx.x == 0 && tid < 32) prefout[tid] = pref[tid];

    // Pack per-(class-pair p, h): [w10 pair][w11 pair][b1 pair][w2diff pair]
    for (int idx = tid; idx < 256; idx += 128) {
        const int p = idx >> 5, h = idx & 31;
        const int c0 = p * 2, c1 = c0 + 1;
        // W1:(C,32,2) c*64+h*2+i ; b1:(C,32) ; W2:(C,2,32) c*64+o*32+h
        sw[idx * 4 + 0] = pk2(W1[c0 * 64 + h * 2 + 0], W1[c1 * 64 + h * 2 + 0]);
        sw[idx * 4 + 1] = pk2(W1[c0 * 64 + h * 2 + 1], W1[c1 * 64 + h * 2 + 1]);
        sw[idx * 4 + 2] = pk2(b1[c0 * 32 + h], b1[c1 * 32 + h]);
        sw[idx * 4 + 3] = pk2(W2[c0 * 64 + h] - W2[c0 * 64 + 32 + h],
                              W2[c1 * 64 + h] - W2[c1 * 64 + 32 + h]);
    }
    if (tid < 16) sb2d[tid] = b2[tid * 2] - b2[tid * 2 + 1];
    __syncthreads();

    // Block = 256 consecutive pixels (256 blocks/image: never straddles).
    const int n0 = blockIdx.x * 256 + tid;  // slot s pixel: n0 + s*128
    const long base = (long)(n0 >> 16) * (16L * 65536) + (n0 & 65535);

    // Phase A: softmax log-denominators: lrs = -lg2(sum exp), so that
    // normalized prob = ex2(x*log2e + lrs).
    float lrs[2], lrg[2];
#pragma unroll
    for (int s = 0; s < 2; s++) {
        const long bs = base + s * 128;
        float ss = 0.f, sg = 0.f;
#pragma unroll
        for (int c = 0; c < 16; c++) {
            ss += ex2f(__ldg(swin + bs + (long)c * 65536) * L2E);
            sg += ex2f(__ldg(gru + bs + (long)c * 65536) * L2E);
        }
        lrs[s] = -lg2f(ss);
        lrg[s] = -lg2f(sg);
    }

    float* myrow = wbuf + tid * STR;  // rows: [slot*128 + tid]

    // Prologue: load pair-0 logits. (c0 half in .x, c1 half in .y)
    float2 csl[2], cgl[2];
#pragma unroll
    for (int s = 0; s < 2; s++) {
        const long o = base + s * 128;
        csl[s] = make_float2(__ldg(swin + o), __ldg(swin + o + 65536));
        cgl[s] = make_float2(__ldg(gru + o), __ldg(gru + o + 65536));
    }

#pragma unroll 1
    for (int p = 0; p < 8; p++) {
        // Prefetch pair p+1 logits (wrap keeps it in-bounds; discarded at p=7).
        const int pn = (p + 1) & 7;
        const long pno = base + (long)(2 * pn) * 65536;
        float2 nsl[2], ngl[2];
#pragma unroll
        for (int s = 0; s < 2; s++) {
            const long o = pno + s * 128;
            nsl[s] = make_float2(__ldg(swin + o), __ldg(swin + o + 65536));
            ngl[s] = make_float2(__ldg(gru + o), __ldg(gru + o + 65536));
        }

        const unsigned long long d2i =
            *reinterpret_cast<const unsigned long long*>(sb2d + 2 * p);
        unsigned long long xp[2], yp[2], d2[2];
#pragma unroll
        for (int s = 0; s < 2; s++) {
            xp[s] = pk2(ex2f(fmaf(csl[s].x, L2E, lrs[s])),
                        ex2f(fmaf(csl[s].y, L2E, lrs[s])));
            yp[s] = pk2(ex2f(fmaf(cgl[s].x, L2E, lrg[s])),
                        ex2f(fmaf(cgl[s].y, L2E, lrg[s])));
            d2[s] = d2i;
        }

        const unsigned long long* wp = sw + p * 128;
#pragma unroll
        for (int h = 0; h < 32; h++) {
            const ulonglong2 wA = *reinterpret_cast<const ulonglong2*>(wp + h * 4);
            const ulonglong2 wB = *reinterpret_cast<const ulonglong2*>(wp + h * 4 + 2);
#pragma unroll
            for (int s = 0; s < 2; s++) {
                unsigned long long t = fma2(wA.x, xp[s], wB.x);
                t = fma2(wA.y, yp[s], t);
                d2[s] = fma2(wB.y, relu2(t), d2[s]);
            }
        }

        const long po = base + (long)(2 * p) * 65536;
#pragma unroll
        for (int s = 0; s < 2; s++) {
            float d0, d1;
            upk2(d2[s], d0, d1);
            const float w0 = __fdividef(1.f, 1.f + ex2f(-d0 * L2E));
            const float w1 = __fdividef(1.f, 1.f + ex2f(-d1 * L2E));
            *reinterpret_cast<float2*>(myrow + s * 128 * STR + 2 * p) =
                make_float2(w0, w1);
            const long o = po + s * 128;
            fused[o] = fmaf(w0, csl[s].x - cgl[s].x, cgl[s].x);
            fused[o + 65536] = fmaf(w1, csl[s].y - cgl[s].y, cgl[s].y);
            csl[s] = nsl[s];
            cgl[s] = ngl[s];
        }
    }

    __syncwarp();  // drain reads only this warp's own rows
    // Drain: per (slot, warp): 32 px * 32 floats = 4KB contiguous in dw.
#pragma unroll
    for (int s = 0; s < 2; s++) {
        const float* rows = wbuf + (s * 128 + warp * 32) * STR;
        const long g = ((long)blockIdx.x * 256 + s * 128 + warp * 32) * 32;
#pragma unroll
        for (int k = 0; k < 8; k++) {
            const int px = 4 * k + (lane >> 3);
            const int pr = lane & 7;
            const float2 w =
                *reinterpret_cast<const float2*>(rows + px * STR + pr * 2);
            *reinterpret_cast<float4*>(dw + g + k * 128 + lane * 4) =
                make_float4(w.x, 1.f - w.x, w.y, 1.f - w.y);
        }
    }
}

extern "C" void kernel_launch(void* const* d_in, const int* in_sizes, int n_in,
                              void* d_out, int out_size) {
    const float* swin = (const float*)d_in[0];
    const float* gru  = (const float*)d_in[1];
    const float* W1   = (const float*)d_in[2];
    const float* b1   = (const float*)d_in[3];
    const float* W2   = (const float*)d_in[4];
    const float* b2   = (const float*)d_in[5];
    const float* pref = (const float*)d_in[6];

    float* out     = (float*)d_out;
    float* fusedp  = out;                     // 8388608
    float* prefout = out + FUSED_ELEMS;       // 32
    float* dwp     = out + FUSED_ELEMS + 32;  // 16777216

    cudaFuncSetAttribute(gate_fuse_kernel,
                         cudaFuncAttributeMaxDynamicSharedMemorySize, SMEM_BYTES);
    gate_fuse_kernel<<<2048, 128, SMEM_BYTES>>>(swin, gru, W1, b1, W2, b2, pref,
                                                fusedp, dwp, prefout);
}

// round 16
// speedup vs baseline: 1.0088x; 1.0088x over previous
#include <cuda_runtime.h>

// CategoryAwareGate: B=8, C=16, H=W=256, HID=32, N = B*H*W = 524288.
// d_out packing (float32): fused_logits[8,16,256,256] (8388608),
// expert_preferences[16,2] (32), dynamic_weights[N,16,2] (16777216).
//
// R15 = R14 + softmax normalization folded into the exponent:
//   exp(x)/ss = ex2(x*log2e - lg2(ss))  -> FFMA+MUFU instead of FMUL+MUFU+FMUL.
// Removes 64 FMULs/thread from the fma pipe (the most-loaded pipe).
// Chassis: block=128, 2 slots/thread, 7 CTAs/SM, logit-prefetch pipeline,
// smem weights, stride-18 dw staging, coalesced drain, in-kernel pref copy.

static constexpr long FUSED_ELEMS = 8L * 16 * 65536;  // 8388608
static constexpr int STR = 18;                         // floats per w-row
static constexpr int SMEM_BYTES = 8192 + 64 + 256 * STR * 4;  // 26688
static constexpr float L2E = 1.4426950408889634f;      // log2(e)

__device__ __forceinline__ unsigned long long pk2(float a, float b) {
    unsigned long long r;
    asm("mov.b64 %0, {%1, %2};" : "=l"(r) : "f"(a), "f"(b));
    return r;
}
__device__ __forceinline__ void upk2(unsigned long long v, float& a, float& b) {
    asm("mov.b64 {%0, %1}, %2;" : "=f"(a), "=f"(b) : "l"(v));
}
__device__ __forceinline__ unsigned long long fma2(unsigned long long a,
                                                   unsigned long long b,
                                                   unsigned long long c) {
    unsigned long long r;
    asm("fma.rn.f32x2 %0, %1, %2, %3;" : "=l"(r) : "l"(a), "l"(b), "l"(c));
    return r;
}
// packed relu: two scalar max.f32 on the halves (no f32x2 min/max in PTX)
__device__ __forceinline__ unsigned long long relu2(unsigned long long v) {
    unsigned long long r;
    asm("{\n\t"
        ".reg .f32 lo, hi;\n\t"
        "mov.b64 {lo, hi}, %1;\n\t"
        "max.f32 lo, lo, 0f00000000;\n\t"
        "max.f32 hi, hi, 0f00000000;\n\t"
        "mov.b64 %0, {lo, hi};\n\t"
        "}" : "=l"(r) : "l"(v));
    return r;
}
__device__ __forceinline__ float ex2f(float x) {
    float r;
    asm("ex2.approx.f32 %0, %1;" : "=f"(r) : "f"(x));
    return r;
}
__device__ __forceinline__ float lg2f(float x) {
    float r;
    asm("lg2.approx.f32 %0, %1;" : "=f"(r) : "f"(x));
    return r;
}

__global__ void __launch_bounds__(128, 7)
gate_fuse_kernel(const float* __restrict__ swin, const float* __restrict__ gru,
                 const float* __restrict__ W1, const float* __restrict__ b1,
                 const float* __restrict__ W2, const float* __restrict__ b2,
                 const float* __restrict__ pref,
                 float* __restrict__ fused, float* __restrict__ dw,
                 float* __restrict__ prefout) {
    extern __shared__ __align__(16) unsigned char smem_raw[];
    unsigned long long* sw = reinterpret_cast<unsigned long long*>(smem_raw);  // 1024 u64
    float* sb2d = reinterpret_cast<float*>(smem_raw + 8192);                   // 16 floats
    float* wbuf = reinterpret_cast<float*>(smem_raw + 8192 + 64);              // 256 x 18

    const int tid = threadIdx.x;
    const int warp = tid >> 5;
    const int lane = tid & 31;

    // expert_preferences pass-through (replaces the memcpy graph node).
    if (blockIdx.x == 0 && tid < 32) prefout[tid] = pref[tid];

    // Pack per-(class-pair p, h): [w10 pair][w11 pair][b1 pair][w2diff pair]
    for (int idx = tid; idx < 256; idx += 128) {
        const int p = idx >> 5, h = idx & 31;
        const int c0 = p * 2, c1 = c0 + 1;
        // W1:(C,32,2) c*64+h*2+i ; b1:(C,32) ; W2:(C,2,32) c*64+o*32+h
        sw[idx * 4 + 0] = pk2(W1[c0 * 64 + h * 2 + 0], W1[c1 * 64 + h * 2 + 0]);
        sw[idx * 4 + 1] = pk2(W1[c0 * 64 + h * 2 + 1], W1[c1 * 64 + h * 2 + 1]);
        sw[idx * 4 + 2] = pk2(b1[c0 * 32 + h], b1[c1 * 32 + h]);
        sw[idx * 4 + 3] = pk2(W2[c0 * 64 + h] - W2[c0 * 64 + 32 + h],
                              W2[c1 * 64 + h] - W2[c1 * 64 + 32 + h]);
    }
    if (tid < 16) sb2d[tid] = b2[tid * 2] - b2[tid * 2 + 1];
    __syncthreads();

    // Block = 256 consecutive pixels (256 blocks/image: never straddles).
    const int n0 = blockIdx.x * 256 + tid;  // slot s pixel: n0 + s*128
    const long base = (long)(n0 >> 16) * (16L * 65536) + (n0 & 65535);

    // Phase A: softmax log-denominators: lrs = -lg2(sum exp), so that
    // normalized prob = ex2(x*log2e + lrs).
    float lrs[2], lrg[2];
#pragma unroll
    for (int s = 0; s < 2; s++) {
        const long bs = base + s * 128;
        float ss = 0.f, sg = 0.f;
#pragma unroll
        for (int c = 0; c < 16; c++) {
            ss += ex2f(__ldg(swin + bs + (long)c * 65536) * L2E);
            sg += ex2f(__ldg(gru + bs + (long)c * 65536) * L2E);
        }
        lrs[s] = -lg2f(ss);
        lrg[s] = -lg2f(sg);
    }

    float* myrow = wbuf + tid * STR;  // rows: [slot*128 + tid]

    // Prologue: load pair-0 logits. (c0 half in .x, c1 half in .y)
    float2 csl[2], cgl[2];
#pragma unroll
    for (int s = 0; s < 2; s++) {
        const long o = base + s * 128;
        csl[s] = make_float2(__ldg(swin + o), __ldg(swin + o + 65536));
        cgl[s] = make_float2(__ldg(gru + o), __ldg(gru + o + 65536));
    }

#pragma unroll 1
    for (int p = 0; p < 8; p++) {
        // Prefetch pair p+1 logits (wrap keeps it in-bounds; discarded at p=7).
        const int pn = (p + 1) & 7;
        const long pno = base + (long)(2 * pn) * 65536;
        float2 nsl[2], ngl[2];
#pragma unroll
        for (int s = 0; s < 2; s++) {
            const long o = pno + s * 128;
            nsl[s] = make_float2(__ldg(swin + o), __ldg(swin + o + 65536));
            ngl[s] = make_float2(__ldg(gru + o), __ldg(gru + o + 65536));
        }

        const unsigned long long d2i =
            *reinterpret_cast<const unsigned long long*>(sb2d + 2 * p);
        unsigned long long xp[2], yp[2], d2[2];
#pragma unroll
        for (int s = 0; s < 2; s++) {
            xp[s] = pk2(ex2f(fmaf(csl[s].x, L2E, lrs[s])),
                        ex2f(fmaf(csl[s].y, L2E, lrs[s])));
            yp[s] = pk2(ex2f(fmaf(cgl[s].x, L2E, lrg[s])),
                        ex2f(fmaf(cgl[s].y, L2E, lrg[s])));
            d2[s] = d2i;
        }

        const unsigned long long* wp = sw + p * 128;
#pragma unroll
        for (int h = 0; h < 32; h++) {
            const ulonglong2 wA = *reinterpret_cast<const ulonglong2*>(wp + h * 4);
            const ulonglong2 wB = *reinterpret_cast<const ulonglong2*>(wp + h * 4 + 2);
#pragma unroll
            for (int s = 0; s < 2; s++) {
                unsigned long long t = fma2(wA.x, xp[s], wB.x);
                t = fma2(wA.y, yp[s], t);
                d2[s] = fma2(wB.y, relu2(t), d2[s]);
            }
        }

        const long po = base + (long)(2 * p) * 65536;
#pragma unroll
        for (int s = 0; s < 2; s++) {
            float d0, d1;
            upk2(d2[s], d0, d1);
            const float w0 = __fdividef(1.f, 1.f + ex2f(-d0 * L2E));
            const float w1 = __fdividef(1.f, 1.f + ex2f(-d1 * L2E));
            *reinterpret_cast<float2*>(myrow + s * 128 * STR + 2 * p) =
                make_float2(w0, w1);
            const long o = po + s * 128;
            fused[o] = fmaf(w0, csl[s].x - cgl[s].x, cgl[s].x);
            fused[o + 65536] = fmaf(w1, csl[s].y - cgl[s].y, cgl[s].y);
            csl[s] = nsl[s];
            cgl[s] = ngl[s];
        }
    }

    __syncwarp();  // drain reads only this warp's own rows
    // Drain: per (slot, warp): 32 px * 32 floats = 4KB contiguous in dw.
#pragma unroll
    for (int s = 0; s < 2; s++) {
        const float* rows = wbuf + (s * 128 + warp * 32) * STR;
        const long g = ((long)blockIdx.x * 256 + s * 128 + warp * 32) * 32;
#pragma unroll
        for (int k = 0; k < 8; k++) {
            const int px = 4 * k + (lane >> 3);
            const int pr = lane & 7;
            const float2 w =
                *reinterpret_cast<const float2*>(rows + px * STR + pr * 2);
            *reinterpret_cast<float4*>(dw + g + k * 128 + lane * 4) =
                make_float4(w.x, 1.f - w.x, w.y, 1.f - w.y);
        }
    }
}

extern "C" void kernel_launch(void* const* d_in, const int* in_sizes, int n_in,
                              void* d_out, int out_size) {
    const float* swin = (const float*)d_in[0];
    const float* gru  = (const float*)d_in[1];
    const float* W1   = (const float*)d_in[2];
    const float* b1   = (const float*)d_in[3];
    const float* W2   = (const float*)d_in[4];
    const float* b2   = (const float*)d_in[5];
    const float* pref = (const float*)d_in[6];

    float* out     = (float*)d_out;
    float* fusedp  = out;                     // 8388608
    float* prefout = out + FUSED_ELEMS;       // 32
    float* dwp     = out + FUSED_ELEMS + 32;  // 16777216

    cudaFuncSetAttribute(gate_fuse_kernel,
                         cudaFuncAttributeMaxDynamicSharedMemorySize, SMEM_BYTES);
    gate_fuse_kernel<<<2048, 128, SMEM_BYTES>>>(swin, gru, W1, b1, W2, b2, pref,
                                                fusedp, dwp, prefout);
}

// round 17
// speedup vs baseline: 1.0161x; 1.0073x over previous
#include <cuda_runtime.h>

// CategoryAwareGate: B=8, C=16, H=W=256, HID=32, N = B*H*W = 524288.
// d_out packing (float32): fused_logits[8,16,256,256] (8388608),
// expert_preferences[16,2] (32), dynamic_weights[N,16,2] (16777216).
//
// R17 = R15 with the p-loop unrolled x2 (cross-iteration ILP: sigmoid/store
// tail of pair p overlaps h-loop of pair p+1) at 5 CTAs/SM (reg cap 102,
// no spill risk). block=128, 2 slots/thread, logit-prefetch rotation,
// smem weights, stride-18 dw staging, coalesced drain, in-kernel pref copy,
// softmax normalization folded into ex2.

static constexpr long FUSED_ELEMS = 8L * 16 * 65536;  // 8388608
static constexpr int STR = 18;                         // floats per w-row
static constexpr int SMEM_BYTES = 8192 + 64 + 256 * STR * 4;  // 26688
static constexpr float L2E = 1.4426950408889634f;      // log2(e)

__device__ __forceinline__ unsigned long long pk2(float a, float b) {
    unsigned long long r;
    asm("mov.b64 %0, {%1, %2};" : "=l"(r) : "f"(a), "f"(b));
    return r;
}
__device__ __forceinline__ void upk2(unsigned long long v, float& a, float& b) {
    asm("mov.b64 {%0, %1}, %2;" : "=f"(a), "=f"(b) : "l"(v));
}
__device__ __forceinline__ unsigned long long fma2(unsigned long long a,
                                                   unsigned long long b,
                                                   unsigned long long c) {
    unsigned long long r;
    asm("fma.rn.f32x2 %0, %1, %2, %3;" : "=l"(r) : "l"(a), "l"(b), "l"(c));
    return r;
}
// packed relu: two scalar max.f32 on the halves (no f32x2 min/max in PTX)
__device__ __forceinline__ unsigned long long relu2(unsigned long long v) {
    unsigned long long r;
    asm("{\n\t"
        ".reg .f32 lo, hi;\n\t"
        "mov.b64 {lo, hi}, %1;\n\t"
        "max.f32 lo, lo, 0f00000000;\n\t"
        "max.f32 hi, hi, 0f00000000;\n\t"
        "mov.b64 %0, {lo, hi};\n\t"
        "}" : "=l"(r) : "l"(v));
    return r;
}
__device__ __forceinline__ float ex2f(float x) {
    float r;
    asm("ex2.approx.f32 %0, %1;" : "=f"(r) : "f"(x));
    return r;
}
__device__ __forceinline__ float lg2f(float x) {
    float r;
    asm("lg2.approx.f32 %0, %1;" : "=f"(r) : "f"(x));
    return r;
}

__global__ void __launch_bounds__(128, 5)
gate_fuse_kernel(const float* __restrict__ swin, const float* __restrict__ gru,
                 const float* __restrict__ W1, const float* __restrict__ b1,
                 const float* __restrict__ W2, const float* __restrict__ b2,
                 const float* __restrict__ pref,
                 float* __restrict__ fused, float* __restrict__ dw,
                 float* __restrict__ prefout) {
    extern __shared__ __align__(16) unsigned char smem_raw[];
    unsigned long long* sw = reinterpret_cast<unsigned long long*>(smem_raw);  // 1024 u64
    float* sb2d = reinterpret_cast<float*>(smem_raw + 8192);                   // 16 floats
    float* wbuf = reinterpret_cast<float*>(smem_raw + 8192 + 64);              // 256 x 18

    const int tid = threadIdx.x;
    const int warp = tid >> 5;
    const int lane = tid & 31;

    // expert_preferences pass-through (replaces the memcpy graph node).
    if (blockIdx.x == 0 && tid < 32) prefout[tid] = pref[tid];

    // Pack per-(class-pair p, h): [w10 pair][w11 pair][b1 pair][w2diff pair]
    for (int idx = tid; idx < 256; idx += 128) {
        const int p = idx >> 5, h = idx & 31;
        const int c0 = p * 2, c1 = c0 + 1;
        // W1:(C,32,2) c*64+h*2+i ; b1:(C,32) ; W2:(C,2,32) c*64+o*32+h
        sw[idx * 4 + 0] = pk2(W1[c0 * 64 + h * 2 + 0], W1[c1 * 64 + h * 2 + 0]);
        sw[idx * 4 + 1] = pk2(W1[c0 * 64 + h * 2 + 1], W1[c1 * 64 + h * 2 + 1]);
        sw[idx * 4 + 2] = pk2(b1[c0 * 32 + h], b1[c1 * 32 + h]);
        sw[idx * 4 + 3] = pk2(W2[c0 * 64 + h] - W2[c0 * 64 + 32 + h],
                              W2[c1 * 64 + h] - W2[c1 * 64 + 32 + h]);
    }
    if (tid < 16) sb2d[tid] = b2[tid * 2] - b2[tid * 2 + 1];
    __syncthreads();

    // Block = 256 consecutive pixels (256 blocks/image: never straddles).
    const int n0 = blockIdx.x * 256 + tid;  // slot s pixel: n0 + s*128
    const long base = (long)(n0 >> 16) * (16L * 65536) + (n0 & 65535);

    // Phase A: softmax log-denominators: lrs = -lg2(sum exp), so that
    // normalized prob = ex2(x*log2e + lrs).
    float lrs[2], lrg[2];
#pragma unroll
    for (int s = 0; s < 2; s++) {
        const long bs = base + s * 128;
        float ss = 0.f, sg = 0.f;
#pragma unroll
        for (int c = 0; c < 16; c++) {
            ss += ex2f(__ldg(swin + bs + (long)c * 65536) * L2E);
            sg += ex2f(__ldg(gru + bs + (long)c * 65536) * L2E);
        }
        lrs[s] = -lg2f(ss);
        lrg[s] = -lg2f(sg);
    }

    float* myrow = wbuf + tid * STR;  // rows: [slot*128 + tid]

    // Prologue: load pair-0 logits. (c0 half in .x, c1 half in .y)
    float2 csl[2], cgl[2];
#pragma unroll
    for (int s = 0; s < 2; s++) {
        const long o = base + s * 128;
        csl[s] = make_float2(__ldg(swin + o), __ldg(swin + o + 65536));
        cgl[s] = make_float2(__ldg(gru + o), __ldg(gru + o + 65536));
    }

#pragma unroll 2
    for (int p = 0; p < 8; p++) {
        // Prefetch pair p+1 logits (wrap keeps it in-bounds; discarded at p=7).
        const int pn = (p + 1) & 7;
        const long pno = base + (long)(2 * pn) * 65536;
        float2 nsl[2], ngl[2];
#pragma unroll
        for (int s = 0; s < 2; s++) {
            const long o = pno + s * 128;
            nsl[s] = make_float2(__ldg(swin + o), __ldg(swin + o + 65536));
            ngl[s] = make_float2(__ldg(gru + o), __ldg(gru + o + 65536));
        }

        const unsigned long long d2i =
            *reinterpret_cast<const unsigned long long*>(sb2d + 2 * p);
        unsigned long long xp[2], yp[2], d2[2];
#pragma unroll
        for (int s = 0; s < 2; s++) {
            xp[s] = pk2(ex2f(fmaf(csl[s].x, L2E, lrs[s])),
                        ex2f(fmaf(csl[s].y, L2E, lrs[s])));
            yp[s] = pk2(ex2f(fmaf(cgl[s].x, L2E, lrg[s])),
                        ex2f(fmaf(cgl[s].y, L2E, lrg[s])));
            d2[s] = d2i;
        }

        const unsigned long long* wp = sw + p * 128;
#pragma unroll
        for (int h = 0; h < 32; h++) {
            const ulonglong2 wA = *reinterpret_cast<const ulonglong2*>(wp + h * 4);
            const ulonglong2 wB = *reinterpret_cast<const ulonglong2*>(wp + h * 4 + 2);
#pragma unroll
            for (int s = 0; s < 2; s++) {
                unsigned long long t = fma2(wA.x, xp[s], wB.x);
                t = fma2(wA.y, yp[s], t);
                d2[s] = fma2(wB.y, relu2(t), d2[s]);
            }
        }

        const long po = base + (long)(2 * p) * 65536;
#pragma unroll
        for (int s = 0; s < 2; s++) {
            float d0, d1;
            upk2(d2[s], d0, d1);
            const float w0 = __fdividef(1.f, 1.f + ex2f(-d0 * L2E));
            const float w1 = __fdividef(1.f, 1.f + ex2f(-d1 * L2E));
            *reinterpret_cast<float2*>(myrow + s * 128 * STR + 2 * p) =
                make_float2(w0, w1);
            const long o = po + s * 128;
            fused[o] = fmaf(w0, csl[s].x - cgl[s].x, cgl[s].x);
            fused[o + 65536] = fmaf(w1, csl[s].y - cgl[s].y, cgl[s].y);
            csl[s] = nsl[s];
            cgl[s] = ngl[s];
        }
    }

    __syncwarp();  // drain reads only this warp's own rows
    // Drain: per (slot, warp): 32 px * 32 floats = 4KB contiguous in dw.
#pragma unroll
    for (int s = 0; s < 2; s++) {
        const float* rows = wbuf + (s * 128 + warp * 32) * STR;
        const long g = ((long)blockIdx.x * 256 + s * 128 + warp * 32) * 32;
#pragma unroll
        for (int k = 0; k < 8; k++) {
            const int px = 4 * k + (lane >> 3);
            const int pr = lane & 7;
            const float2 w =
                *reinterpret_cast<const float2*>(rows + px * STR + pr * 2);
            *reinterpret_cast<float4*>(dw + g + k * 128 + lane * 4) =
                make_float4(w.x, 1.f - w.x, w.y, 1.f - w.y);
        }
    }
}

extern "C" void kernel_launch(void* const* d_in, const int* in_sizes, int n_in,
                              void* d_out, int out_size) {
    const float* swin = (const float*)d_in[0];
    const float* gru  = (const float*)d_in[1];
    const float* W1   = (const float*)d_in[2];
    const float* b1   = (const float*)d_in[3];
    const float* W2   = (const float*)d_in[4];
    const float* b2   = (const float*)d_in[5];
    const float* pref = (const float*)d_in[6];

    float* out     = (float*)d_out;
    float* fusedp  = out;                     // 8388608
    float* prefout = out + FUSED_ELEMS;       // 32
    float* dwp     = out + FUSED_ELEMS + 32;  // 16777216

    cudaFuncSetAttribute(gate_fuse_kernel,
                         cudaFuncAttributeMaxDynamicSharedMemorySize, SMEM_BYTES);
    gate_fuse_kernel<<<2048, 128, SMEM_BYTES>>>(swin, gru, W1, b1, W2, b2, pref,
                                                fusedp, dwp, prefout);
}